// round 1
// baseline (speedup 1.0000x reference)
#include <cuda_runtime.h>
#include <math.h>

// Problem dims
constexpr int B_ = 4, T_ = 2048, DM_ = 1024, H_ = 16, D_ = 64;
constexpr int NROWS = B_ * T_;          // 8192
constexpr int STATE_ELEMS = B_ * H_ * D_ * D_;  // 262144

// Scratch (device globals: allocation-free)
__device__ float g_Q[NROWS * DM_];
__device__ float g_K[NROWS * DM_];
__device__ float g_V[NROWS * DM_];
__device__ float g_Y[NROWS * DM_];
__device__ float g_alpha[NROWS * H_];
__device__ float g_beta[NROWS * H_];
__device__ float g_Sdump[STATE_ELEMS];

// ---------------------------------------------------------------------------
// SGEMM: C[8192,1024] = A[8192,1024] @ Bm[1024,1024], all row-major fp32.
// 128x128 block, BK=16, 256 threads, 8x8 per thread.
// ---------------------------------------------------------------------------
__global__ __launch_bounds__(256) void sgemm128(const float* __restrict__ A,
                                                const float* __restrict__ Bm,
                                                float* __restrict__ C) {
    __shared__ float As[16][132];   // padded (+4) to break store conflicts, keeps 16B align
    __shared__ float Bs[16][128];

    const int tid = threadIdx.x;
    const int row0 = blockIdx.y * 128;
    const int col0 = blockIdx.x * 128;

    float acc[8][8];
#pragma unroll
    for (int i = 0; i < 8; ++i)
#pragma unroll
        for (int j = 0; j < 8; ++j) acc[i][j] = 0.f;

    const int tm = (tid >> 4) << 3;   // 0..120
    const int tn = (tid & 15) << 3;

    for (int kt = 0; kt < 1024; kt += 16) {
        float4 aReg[2], bReg[2];
#pragma unroll
        for (int l = 0; l < 2; ++l) {
            int idx = tid + l * 256;            // 0..511
            int r = idx >> 2, c = (idx & 3) << 2;
            aReg[l] = *(const float4*)(A + (size_t)(row0 + r) * 1024 + kt + c);
            int bk = idx >> 5, bc = (idx & 31) << 2;
            bReg[l] = *(const float4*)(Bm + (size_t)(kt + bk) * 1024 + col0 + bc);
        }
        __syncthreads();   // previous tile compute done
#pragma unroll
        for (int l = 0; l < 2; ++l) {
            int idx = tid + l * 256;
            int r = idx >> 2, c = (idx & 3) << 2;
            As[c + 0][r] = aReg[l].x;
            As[c + 1][r] = aReg[l].y;
            As[c + 2][r] = aReg[l].z;
            As[c + 3][r] = aReg[l].w;
            int bk = idx >> 5, bc = (idx & 31) << 2;
            *(float4*)(&Bs[bk][bc]) = bReg[l];
        }
        __syncthreads();
#pragma unroll
        for (int k = 0; k < 16; ++k) {
            float ra[8], rb[8];
#pragma unroll
            for (int i = 0; i < 8; ++i) ra[i] = As[k][tm + i];
#pragma unroll
            for (int j = 0; j < 8; ++j) rb[j] = Bs[k][tn + j];
#pragma unroll
            for (int i = 0; i < 8; ++i)
#pragma unroll
                for (int j = 0; j < 8; ++j)
                    acc[i][j] = fmaf(ra[i], rb[j], acc[i][j]);
        }
    }

#pragma unroll
    for (int i = 0; i < 8; ++i) {
        float4* dst = (float4*)(C + (size_t)(row0 + tm + i) * 1024 + col0 + tn);
        dst[0] = make_float4(acc[i][0], acc[i][1], acc[i][2], acc[i][3]);
        dst[1] = make_float4(acc[i][4], acc[i][5], acc[i][6], acc[i][7]);
    }
}

// ---------------------------------------------------------------------------
// Gates: alpha/beta[n][h] = sigmoid(x[n] . W[:,h] + bias[h])
// One block per row n; 256 threads; 32 outputs (16 alpha + 16 beta),
// 8 threads per output.
// ---------------------------------------------------------------------------
__global__ __launch_bounds__(256) void gates_kernel(
    const float* __restrict__ x, const float* __restrict__ Wa,
    const float* __restrict__ ba, const float* __restrict__ Wb,
    const float* __restrict__ bb, float* __restrict__ alpha,
    float* __restrict__ beta) {
    __shared__ float xs[1024];
    const int n = blockIdx.x;
    const int tid = threadIdx.x;
    ((float4*)xs)[tid] = ((const float4*)(x + (size_t)n * 1024))[tid];
    __syncthreads();

    const int o = tid >> 3;       // 0..31
    const int lane8 = tid & 7;
    const int g = o >> 4, h = o & 15;
    const float* W = g ? Wb : Wa;
    float sum = 0.f;
#pragma unroll 8
    for (int d = lane8; d < 1024; d += 8)
        sum = fmaf(xs[d], W[d * 16 + h], sum);
    sum += __shfl_xor_sync(~0u, sum, 1);
    sum += __shfl_xor_sync(~0u, sum, 2);
    sum += __shfl_xor_sync(~0u, sum, 4);
    if (lane8 == 0) {
        float z = sum + (g ? bb[h] : ba[h]);
        float r = 1.f / (1.f + expf(-z));
        (g ? beta : alpha)[(size_t)n * 16 + h] = r;
    }
}

// ---------------------------------------------------------------------------
// K normalize: one warp per (n,h) 64-vector; K /= max(||K||, 1e-12)
// ---------------------------------------------------------------------------
__global__ __launch_bounds__(256) void knorm_kernel(float* __restrict__ K) {
    const int w = (int)((blockIdx.x * blockDim.x + threadIdx.x) >> 5);
    const int lane = threadIdx.x & 31;
    if (w >= NROWS * H_) return;
    float2* p = (float2*)(K + (size_t)w * 64);
    float2 v = p[lane];
    float ss = v.x * v.x + v.y * v.y;
#pragma unroll
    for (int m = 16; m; m >>= 1) ss += __shfl_xor_sync(~0u, ss, m);
    float inv = 1.f / fmaxf(sqrtf(ss), 1e-12f);
    v.x *= inv;
    v.y *= inv;
    p[lane] = v;
}

// ---------------------------------------------------------------------------
// Sequential scan. One block per (b,h). 256 threads: thread owns row
// i = tid/4 and 16 columns (jg = tid%4). State fully register-resident.
// Input q/k/v/a/b staged in chunks of 16 steps, double-buffered.
// ---------------------------------------------------------------------------
__global__ __launch_bounds__(256) void scan_kernel(
    const float* __restrict__ Q, const float* __restrict__ K,
    const float* __restrict__ V, const float* __restrict__ alpha,
    const float* __restrict__ beta, const float* __restrict__ S0,
    float* __restrict__ Y, float* __restrict__ Sout) {
    constexpr int CH = 16;
    __shared__ float cq[2][CH][64];
    __shared__ float ck[2][CH][64];
    __shared__ float cv[2][CH][64];
    __shared__ float ca[2][CH];
    __shared__ float cb[2][CH];

    const int tid = threadIdx.x;
    const int bh = blockIdx.x;          // 0..63
    const int b = bh >> 4, h = bh & 15;
    const int i = tid >> 2;             // row 0..63
    const int jg = tid & 3;             // column group
    const int j0 = jg << 4;

    float4 s4[4];
    {
        const float4* sp = (const float4*)(S0 + ((size_t)bh * 64 + i) * 64 + j0);
        s4[0] = sp[0]; s4[1] = sp[1]; s4[2] = sp[2]; s4[3] = sp[3];
    }

    const size_t rowbase = (size_t)b * T_ * DM_ + (size_t)h * 64;
    const int s_ld = tid >> 4;           // step within chunk for loader role
    const int f_ld = (tid & 15) << 2;    // float offset within 64

    auto load_chunk = [&](int t0, int buf) {
        size_t off = rowbase + (size_t)(t0 + s_ld) * DM_ + f_ld;
        *(float4*)(&cq[buf][s_ld][f_ld]) = *(const float4*)(Q + off);
        *(float4*)(&ck[buf][s_ld][f_ld]) = *(const float4*)(K + off);
        *(float4*)(&cv[buf][s_ld][f_ld]) = *(const float4*)(V + off);
        if (tid < CH)
            ca[buf][tid] = alpha[((size_t)b * T_ + t0 + tid) * H_ + h];
        else if (tid < 2 * CH)
            cb[buf][tid - CH] = beta[((size_t)b * T_ + t0 + tid - CH) * H_ + h];
    };

    const int nch = T_ / CH;
    load_chunk(0, 0);
    __syncthreads();

    for (int c = 0; c < nch; ++c) {
        const int buf = c & 1;
        if (c + 1 < nch) load_chunk((c + 1) * CH, buf ^ 1);

#pragma unroll 4
        for (int s = 0; s < CH; ++s) {
            const float a = ca[buf][s];
            const float bg = cb[buf][s];
            const float bv = bg * cv[buf][s][i];
            const float4* kp = (const float4*)(&ck[buf][s][j0]);
            const float4* qp = (const float4*)(&cq[buf][s][j0]);
            float partial = 0.f;
#pragma unroll
            for (int v = 0; v < 4; ++v) {
                float4 kk = kp[v];
                float4 qq = qp[v];
                s4[v].x = fmaf(a, s4[v].x, bv * kk.x); partial = fmaf(s4[v].x, qq.x, partial);
                s4[v].y = fmaf(a, s4[v].y, bv * kk.y); partial = fmaf(s4[v].y, qq.y, partial);
                s4[v].z = fmaf(a, s4[v].z, bv * kk.z); partial = fmaf(s4[v].z, qq.z, partial);
                s4[v].w = fmaf(a, s4[v].w, bv * kk.w); partial = fmaf(s4[v].w, qq.w, partial);
            }
            partial += __shfl_xor_sync(~0u, partial, 1);
            partial += __shfl_xor_sync(~0u, partial, 2);
            if (jg == 0)
                Y[rowbase + (size_t)(c * CH + s) * DM_ + i] = partial;
        }
        __syncthreads();   // loads for c+1 done AND reads of buf done
    }

    // final state
    float4* so = (float4*)(Sout + ((size_t)bh * 64 + i) * 64 + j0);
    so[0] = s4[0]; so[1] = s4[1]; so[2] = s4[2]; so[3] = s4[3];
}

// ---------------------------------------------------------------------------
extern "C" void kernel_launch(void* const* d_in, const int* in_sizes, int n_in,
                              void* d_out, int out_size) {
    (void)in_sizes; (void)n_in;
    const float* x  = (const float*)d_in[0];
    const float* S0 = (const float*)d_in[1];
    const float* Wq = (const float*)d_in[2];
    const float* Wk = (const float*)d_in[3];
    const float* Wv = (const float*)d_in[4];
    const float* Wa = (const float*)d_in[5];
    const float* ba = (const float*)d_in[6];
    const float* Wb = (const float*)d_in[7];
    const float* bb = (const float*)d_in[8];
    const float* Wo = (const float*)d_in[9];
    float* out = (float*)d_out;

    float *Qd, *Kd, *Vd, *Yd, *al, *be, *Sdump;
    cudaGetSymbolAddress((void**)&Qd, g_Q);
    cudaGetSymbolAddress((void**)&Kd, g_K);
    cudaGetSymbolAddress((void**)&Vd, g_V);
    cudaGetSymbolAddress((void**)&Yd, g_Y);
    cudaGetSymbolAddress((void**)&al, g_alpha);
    cudaGetSymbolAddress((void**)&be, g_beta);
    cudaGetSymbolAddress((void**)&Sdump, g_Sdump);

    // Final state goes after `out` if the output buffer holds both.
    float* Sout = (out_size >= NROWS * DM_ + STATE_ELEMS)
                      ? out + (size_t)NROWS * DM_
                      : Sdump;

    dim3 ggrid(1024 / 128, NROWS / 128);   // (8, 64)

    sgemm128<<<ggrid, 256>>>(x, Wq, Qd);
    sgemm128<<<ggrid, 256>>>(x, Wk, Kd);
    sgemm128<<<ggrid, 256>>>(x, Wv, Vd);
    gates_kernel<<<NROWS, 256>>>(x, Wa, ba, Wb, bb, al, be);
    knorm_kernel<<<(NROWS * H_ * 32) / 256, 256>>>(Kd);
    scan_kernel<<<B_ * H_, 256>>>(Qd, Kd, Vd, al, be, S0, Yd, Sout);
    sgemm128<<<ggrid, 256>>>(Yd, Wo, out);
}

// round 3
// speedup vs baseline: 1.5838x; 1.5838x over previous
#include <cuda_runtime.h>
#include <cuda_bf16.h>
#include <cstdint>
#include <math.h>

// Problem dims
constexpr int B_ = 4, T_ = 2048, DM_ = 1024, H_ = 16, D_ = 64;
constexpr int NROWS = B_ * T_;           // 8192
constexpr int KP = 3072;                 // 3-term split: [ah|al|ah] . [bh|bh|bl]
constexpr int STATE_ELEMS = B_ * H_ * D_ * D_;

// ---------------- scratch (device globals; allocation-free) ----------------
__device__ float g_Q[NROWS * DM_];
__device__ float g_K[NROWS * DM_];
__device__ float g_V[NROWS * DM_];
__device__ float g_Y[NROWS * DM_];
__device__ float g_alpha[NROWS * H_];
__device__ float g_beta[NROWS * H_];
__device__ float g_Sdump[STATE_ELEMS];
__device__ float g_Wab32[32 * DM_];
__device__ __nv_bfloat16 g_A2[(size_t)NROWS * KP];
__device__ __nv_bfloat16 g_Y2[(size_t)NROWS * KP];
__device__ __nv_bfloat16 g_Wtq[(size_t)DM_ * KP];
__device__ __nv_bfloat16 g_Wtk[(size_t)DM_ * KP];
__device__ __nv_bfloat16 g_Wtv[(size_t)DM_ * KP];
__device__ __nv_bfloat16 g_Wto[(size_t)DM_ * KP];

// ---------------------------------------------------------------------------
// bf16 mma.sync GEMM: C[8192,1024] = A'[8192,3072] @ B'[1024,3072]^T
// CTA tile 128x256, 8 warps (2M x 4N), warp tile 64x64, Kc=32 double-buffered
// cp.async. smem rows padded to 40 halves (80B) for conflict-free ldmatrix.
// ---------------------------------------------------------------------------
__global__ __launch_bounds__(256, 1) void gemm_mma(const __nv_bfloat16* __restrict__ A,
                                                   const __nv_bfloat16* __restrict__ Bw,
                                                   float* __restrict__ C) {
    extern __shared__ char sm[];
    const int tid = threadIdx.x;
    const int lane = tid & 31, wid = tid >> 5;
    const int wm = wid & 1, wn = wid >> 1;       // 2 x 4 warp grid
    const int row0 = blockIdx.y * 128;
    const int col0 = blockIdx.x * 256;

    uint32_t sb;
    asm("{ .reg .u64 t; cvta.to.shared.u64 t, %1; cvt.u32.u64 %0, t; }" : "=r"(sb) : "l"(sm));

    // smem byte offsets: A bufs 128*40*2 = 10240 each; B bufs 256*40*2 = 20480
    const uint32_t A_OFF0 = 0u, A_OFF1 = 10240u;
    const uint32_t B_OFF0 = 20480u, B_OFF1 = 41440u - 480u; // 40960
    (void)B_OFF1;

    float acc[4][8][4];
#pragma unroll
    for (int i = 0; i < 4; ++i)
#pragma unroll
        for (int j = 0; j < 8; ++j)
#pragma unroll
            for (int q = 0; q < 4; ++q) acc[i][j][q] = 0.f;

    auto load_chunk = [&](int c, int buf) {
        const __nv_bfloat16* gA = A + (size_t)row0 * KP + c * 32;
        uint32_t ab = sb + (buf ? A_OFF1 : A_OFF0);
#pragma unroll
        for (int l = 0; l < 2; ++l) {
            int idx = tid + (l << 8);
            int r = idx >> 2, s = idx & 3;
            uint32_t so = ab + (uint32_t)(r * 40 + s * 8) * 2;
            const void* gp = gA + (size_t)r * KP + s * 8;
            asm volatile("cp.async.cg.shared.global [%0], [%1], 16;" :: "r"(so), "l"(gp));
        }
        const __nv_bfloat16* gB = Bw + (size_t)col0 * KP + c * 32;
        uint32_t bbx = sb + (buf ? (B_OFF0 + 20480u) : B_OFF0);
#pragma unroll
        for (int l = 0; l < 4; ++l) {
            int idx = tid + (l << 8);
            int n = idx >> 2, s = idx & 3;
            uint32_t so = bbx + (uint32_t)(n * 40 + s * 8) * 2;
            const void* gp = gB + (size_t)n * KP + s * 8;
            asm volatile("cp.async.cg.shared.global [%0], [%1], 16;" :: "r"(so), "l"(gp));
        }
        asm volatile("cp.async.commit_group;" ::: "memory");
    };

    // per-lane ldmatrix base offsets (in halves)
    // A x4: lanes 0-7 -> m+0..7 @k0 | 8-15 -> m+8..15 @k0 | 16-23 -> m..7 @k8 | 24-31 -> m+8..15 @k8
    const uint32_t a_base = (uint32_t)((wm * 64 + (lane & 15)) * 40 + ((lane >> 4) << 3));
    // B x4: lanes 0-7 -> n0..7 @k0 | 8-15 -> n0..7 @k8 | 16-23 -> n8..15 @k0 | 24-31 -> n8..15 @k8
    const uint32_t b_base = (uint32_t)((wn * 64 + (((lane >> 4) & 1) << 3) + (lane & 7)) * 40 +
                                       (((lane >> 3) & 1) << 3));

    load_chunk(0, 0);

    constexpr int NCH = KP / 32;  // 96
    for (int c = 0; c < NCH; ++c) {
        const int buf = c & 1;
        if (c + 1 < NCH) {
            load_chunk(c + 1, buf ^ 1);
            asm volatile("cp.async.wait_group 1;" ::: "memory");
        } else {
            asm volatile("cp.async.wait_group 0;" ::: "memory");
        }
        __syncthreads();

        const uint32_t ab = sb + (buf ? A_OFF1 : A_OFF0);
        const uint32_t bbs = sb + (buf ? (B_OFF0 + 20480u) : B_OFF0);
#pragma unroll
        for (int ks = 0; ks < 2; ++ks) {
            uint32_t af[4][4];
#pragma unroll
            for (int mi = 0; mi < 4; ++mi) {
                uint32_t addr = ab + (a_base + (uint32_t)(mi * 16 * 40 + ks * 16)) * 2;
                asm volatile("ldmatrix.sync.aligned.m8n8.x4.shared.b16 {%0,%1,%2,%3}, [%4];"
                             : "=r"(af[mi][0]), "=r"(af[mi][1]), "=r"(af[mi][2]), "=r"(af[mi][3])
                             : "r"(addr));
            }
            uint32_t bf[8][2];
#pragma unroll
            for (int nb = 0; nb < 4; ++nb) {
                uint32_t addr = bbs + (b_base + (uint32_t)(nb * 16 * 40 + ks * 16)) * 2;
                asm volatile("ldmatrix.sync.aligned.m8n8.x4.shared.b16 {%0,%1,%2,%3}, [%4];"
                             : "=r"(bf[2 * nb][0]), "=r"(bf[2 * nb][1]),
                               "=r"(bf[2 * nb + 1][0]), "=r"(bf[2 * nb + 1][1])
                             : "r"(addr));
            }
#pragma unroll
            for (int mi = 0; mi < 4; ++mi)
#pragma unroll
                for (int ni = 0; ni < 8; ++ni) {
                    asm volatile(
                        "mma.sync.aligned.m16n8k16.row.col.f32.bf16.bf16.f32 "
                        "{%0,%1,%2,%3}, {%4,%5,%6,%7}, {%8,%9}, {%0,%1,%2,%3};"
                        : "+f"(acc[mi][ni][0]), "+f"(acc[mi][ni][1]),
                          "+f"(acc[mi][ni][2]), "+f"(acc[mi][ni][3])
                        : "r"(af[mi][0]), "r"(af[mi][1]), "r"(af[mi][2]), "r"(af[mi][3]),
                          "r"(bf[ni][0]), "r"(bf[ni][1]));
                }
        }
        __syncthreads();
    }

    // epilogue: thread t of each atom holds (m = t/4 [+8], n = (t%4)*2, +1)
    const int rb = row0 + wm * 64 + (lane >> 2);
    const int cb = col0 + wn * 64 + (lane & 3) * 2;
#pragma unroll
    for (int mi = 0; mi < 4; ++mi)
#pragma unroll
        for (int ni = 0; ni < 8; ++ni) {
            int r = rb + mi * 16, cc = cb + ni * 8;
            *(float2*)(C + (size_t)r * 1024 + cc) = make_float2(acc[mi][ni][0], acc[mi][ni][1]);
            *(float2*)(C + (size_t)(r + 8) * 1024 + cc) =
                make_float2(acc[mi][ni][2], acc[mi][ni][3]);
        }
}

// ---------------------------------------------------------------------------
// fp32 -> 3-term split bf16: out[m] = [hi(1024) | lo(1024) | hi(1024)]
// ---------------------------------------------------------------------------
__global__ __launch_bounds__(256) void convert_split3(const float* __restrict__ in,
                                                      __nv_bfloat16* __restrict__ out) {
    size_t i = (size_t)blockIdx.x * 256 + threadIdx.x;   // float4 group id
    float4 v = ((const float4*)in)[i];
    size_t m = i >> 8;
    int k4 = (int)(i & 255) << 2;
    __nv_bfloat16 h0 = __float2bfloat16(v.x), h1 = __float2bfloat16(v.y);
    __nv_bfloat16 h2 = __float2bfloat16(v.z), h3 = __float2bfloat16(v.w);
    __nv_bfloat16 l0 = __float2bfloat16(v.x - __bfloat162float(h0));
    __nv_bfloat16 l1 = __float2bfloat16(v.y - __bfloat162float(h1));
    __nv_bfloat16 l2 = __float2bfloat16(v.z - __bfloat162float(h2));
    __nv_bfloat16 l3 = __float2bfloat16(v.w - __bfloat162float(h3));
    __nv_bfloat162 hA = __halves2bfloat162(h0, h1), hB = __halves2bfloat162(h2, h3);
    __nv_bfloat162 lA = __halves2bfloat162(l0, l1), lB = __halves2bfloat162(l2, l3);
    __nv_bfloat162* o0 = (__nv_bfloat162*)(out + m * KP + k4);
    o0[0] = hA; o0[1] = hB;
    __nv_bfloat162* o1 = (__nv_bfloat162*)(out + m * KP + 1024 + k4);
    o1[0] = lA; o1[1] = lB;
    __nv_bfloat162* o2 = (__nv_bfloat162*)(out + m * KP + 2048 + k4);
    o2[0] = hA; o2[1] = hB;
}

// W[1024][1024] fp32 -> B'[n][3072] = [hi | hi | lo]  (transposed, K-major)
__global__ __launch_bounds__(256) void transpose_split3(const float* __restrict__ W,
                                                        __nv_bfloat16* __restrict__ out) {
    __shared__ float s[32][33];
    const int tx = threadIdx.x & 31, ty = threadIdx.x >> 5;
    const int k0 = blockIdx.y << 5, n0 = blockIdx.x << 5;
#pragma unroll
    for (int r = 0; r < 32; r += 8)
        s[ty + r][tx] = W[(size_t)(k0 + ty + r) * 1024 + n0 + tx];
    __syncthreads();
#pragma unroll
    for (int r = 0; r < 32; r += 8) {
        const int n = n0 + ty + r, k = k0 + tx;
        float v = s[tx][ty + r];
        __nv_bfloat16 h = __float2bfloat16(v);
        __nv_bfloat16 l = __float2bfloat16(v - __bfloat162float(h));
        out[(size_t)n * KP + k] = h;
        out[(size_t)n * KP + 1024 + k] = h;
        out[(size_t)n * KP + 2048 + k] = l;
    }
}

// Wa/Wb [1024][16] -> Wt32[32][1024] fp32 (row o<16: Wa col o; else Wb col o-16)
__global__ __launch_bounds__(256) void gates_prep32(const float* __restrict__ Wa,
                                                    const float* __restrict__ Wb,
                                                    float* __restrict__ out) {
    const int o = blockIdx.x;
    const float* W = (o < 16) ? Wa : Wb;
    const int h = o & 15;
    for (int k = threadIdx.x; k < 1024; k += 256)
        out[(size_t)o * 1024 + k] = W[k * 16 + h];
}

// ---------------------------------------------------------------------------
// Gates: logits = x @ Wt32^T, + bias, sigmoid. Block = 64 rows x 32 outputs.
// ---------------------------------------------------------------------------
__global__ __launch_bounds__(256) void gates64(const float* __restrict__ x,
                                               const float* __restrict__ Wt,
                                               const float* __restrict__ ba,
                                               const float* __restrict__ bb,
                                               float* __restrict__ alpha,
                                               float* __restrict__ beta) {
    __shared__ float xs[64][64];
    __shared__ float ws[32][65];
    const int tid = threadIdx.x;
    const int row0 = blockIdx.x * 64;
    const int rg = tid >> 5;     // warp-uniform row group
    const int o = tid & 31;

    float acc[8];
#pragma unroll
    for (int p = 0; p < 8; ++p) acc[p] = 0.f;

    for (int kc = 0; kc < 16; ++kc) {
        __syncthreads();
#pragma unroll
        for (int l = 0; l < 4; ++l) {
            int idx = tid + (l << 8);
            int r = idx >> 4, q = idx & 15;
            float4 v = *(const float4*)(x + (size_t)(row0 + r) * 1024 + kc * 64 + q * 4);
            *(float4*)(&xs[r][q * 4]) = v;
        }
#pragma unroll
        for (int l = 0; l < 2; ++l) {
            int idx = tid + (l << 8);
            int r = idx >> 4, q = idx & 15;
            float4 v = *(const float4*)(Wt + (size_t)r * 1024 + kc * 64 + q * 4);
            ws[r][q * 4 + 0] = v.x; ws[r][q * 4 + 1] = v.y;
            ws[r][q * 4 + 2] = v.z; ws[r][q * 4 + 3] = v.w;
        }
        __syncthreads();
#pragma unroll 8
        for (int k = 0; k < 64; ++k) {
            float wv = ws[o][k];
#pragma unroll
            for (int p = 0; p < 8; ++p)
                acc[p] = fmaf(xs[rg * 8 + p][k], wv, acc[p]);
        }
    }

    const float bias = (o < 16) ? ba[o] : bb[o - 16];
#pragma unroll
    for (int p = 0; p < 8; ++p) {
        float r = 1.f / (1.f + expf(-(acc[p] + bias)));
        int row = row0 + rg * 8 + p;
        if (o < 16) alpha[(size_t)row * 16 + o] = r;
        else        beta[(size_t)row * 16 + (o - 16)] = r;
    }
}

// ---------------------------------------------------------------------------
// K normalize: one warp per (n,h) 64-vector
// ---------------------------------------------------------------------------
__global__ __launch_bounds__(256) void knorm_kernel(float* __restrict__ K) {
    const int w = (int)((blockIdx.x * blockDim.x + threadIdx.x) >> 5);
    const int lane = threadIdx.x & 31;
    if (w >= NROWS * H_) return;
    float2* p = (float2*)(K + (size_t)w * 64);
    float2 v = p[lane];
    float ss = v.x * v.x + v.y * v.y;
#pragma unroll
    for (int m = 16; m; m >>= 1) ss += __shfl_xor_sync(~0u, ss, m);
    float inv = 1.f / fmaxf(sqrtf(ss), 1e-12f);
    v.x *= inv; v.y *= inv;
    p[lane] = v;
}

// ---------------------------------------------------------------------------
// Sequential scan (proven in R1)
// ---------------------------------------------------------------------------
__global__ __launch_bounds__(256) void scan_kernel(
    const float* __restrict__ Q, const float* __restrict__ K,
    const float* __restrict__ V, const float* __restrict__ alpha,
    const float* __restrict__ beta, const float* __restrict__ S0,
    float* __restrict__ Y, float* __restrict__ Sout) {
    constexpr int CH = 16;
    __shared__ float cq[2][CH][64];
    __shared__ float ck[2][CH][64];
    __shared__ float cv[2][CH][64];
    __shared__ float ca[2][CH];
    __shared__ float cb[2][CH];

    const int tid = threadIdx.x;
    const int bh = blockIdx.x;
    const int b = bh >> 4, h = bh & 15;
    const int i = tid >> 2;
    const int jg = tid & 3;
    const int j0 = jg << 4;

    float4 s4[4];
    {
        const float4* sp = (const float4*)(S0 + ((size_t)bh * 64 + i) * 64 + j0);
        s4[0] = sp[0]; s4[1] = sp[1]; s4[2] = sp[2]; s4[3] = sp[3];
    }

    const size_t rowbase = (size_t)b * T_ * DM_ + (size_t)h * 64;
    const int s_ld = tid >> 4;
    const int f_ld = (tid & 15) << 2;

    auto load_chunk = [&](int t0, int buf) {
        size_t off = rowbase + (size_t)(t0 + s_ld) * DM_ + f_ld;
        *(float4*)(&cq[buf][s_ld][f_ld]) = *(const float4*)(Q + off);
        *(float4*)(&ck[buf][s_ld][f_ld]) = *(const float4*)(K + off);
        *(float4*)(&cv[buf][s_ld][f_ld]) = *(const float4*)(V + off);
        if (tid < CH)
            ca[buf][tid] = alpha[((size_t)b * T_ + t0 + tid) * H_ + h];
        else if (tid < 2 * CH)
            cb[buf][tid - CH] = beta[((size_t)b * T_ + t0 + tid - CH) * H_ + h];
    };

    const int nch = T_ / CH;
    load_chunk(0, 0);
    __syncthreads();

    for (int c = 0; c < nch; ++c) {
        const int buf = c & 1;
        if (c + 1 < nch) load_chunk((c + 1) * CH, buf ^ 1);

#pragma unroll 4
        for (int s = 0; s < CH; ++s) {
            const float a = ca[buf][s];
            const float bg = cb[buf][s];
            const float bv = bg * cv[buf][s][i];
            const float4* kp = (const float4*)(&ck[buf][s][j0]);
            const float4* qp = (const float4*)(&cq[buf][s][j0]);
            float partial = 0.f;
#pragma unroll
            for (int v = 0; v < 4; ++v) {
                float4 kk = kp[v];
                float4 qq = qp[v];
                s4[v].x = fmaf(a, s4[v].x, bv * kk.x); partial = fmaf(s4[v].x, qq.x, partial);
                s4[v].y = fmaf(a, s4[v].y, bv * kk.y); partial = fmaf(s4[v].y, qq.y, partial);
                s4[v].z = fmaf(a, s4[v].z, bv * kk.z); partial = fmaf(s4[v].z, qq.z, partial);
                s4[v].w = fmaf(a, s4[v].w, bv * kk.w); partial = fmaf(s4[v].w, qq.w, partial);
            }
            partial += __shfl_xor_sync(~0u, partial, 1);
            partial += __shfl_xor_sync(~0u, partial, 2);
            if (jg == 0)
                Y[rowbase + (size_t)(c * CH + s) * DM_ + i] = partial;
        }
        __syncthreads();
    }

    float4* so = (float4*)(Sout + ((size_t)bh * 64 + i) * 64 + j0);
    so[0] = s4[0]; so[1] = s4[1]; so[2] = s4[2]; so[3] = s4[3];
}

// ---------------------------------------------------------------------------
extern "C" void kernel_launch(void* const* d_in, const int* in_sizes, int n_in,
                              void* d_out, int out_size) {
    (void)in_sizes; (void)n_in;
    const float* x  = (const float*)d_in[0];
    const float* S0 = (const float*)d_in[1];
    const float* Wq = (const float*)d_in[2];
    const float* Wk = (const float*)d_in[3];
    const float* Wv = (const float*)d_in[4];
    const float* Wa = (const float*)d_in[5];
    const float* ba = (const float*)d_in[6];
    const float* Wb = (const float*)d_in[7];
    const float* bb = (const float*)d_in[8];
    const float* Wo = (const float*)d_in[9];
    float* out = (float*)d_out;

    float *Qd, *Kd, *Vd, *Yd, *al, *be, *Sdump, *Wab32;
    __nv_bfloat16 *A2, *Y2, *Wtq, *Wtk, *Wtv, *Wto;
    cudaGetSymbolAddress((void**)&Qd, g_Q);
    cudaGetSymbolAddress((void**)&Kd, g_K);
    cudaGetSymbolAddress((void**)&Vd, g_V);
    cudaGetSymbolAddress((void**)&Yd, g_Y);
    cudaGetSymbolAddress((void**)&al, g_alpha);
    cudaGetSymbolAddress((void**)&be, g_beta);
    cudaGetSymbolAddress((void**)&Sdump, g_Sdump);
    cudaGetSymbolAddress((void**)&Wab32, g_Wab32);
    cudaGetSymbolAddress((void**)&A2, g_A2);
    cudaGetSymbolAddress((void**)&Y2, g_Y2);
    cudaGetSymbolAddress((void**)&Wtq, g_Wtq);
    cudaGetSymbolAddress((void**)&Wtk, g_Wtk);
    cudaGetSymbolAddress((void**)&Wtv, g_Wtv);
    cudaGetSymbolAddress((void**)&Wto, g_Wto);

    float* Sout = (out_size >= NROWS * DM_ + STATE_ELEMS) ? out + (size_t)NROWS * DM_ : Sdump;

    constexpr int GSMEM = 2 * 10240 + 2 * 20480;   // 61440
    static bool attr_set = false;
    if (!attr_set) {
        cudaFuncSetAttribute(gemm_mma, cudaFuncAttributeMaxDynamicSharedMemorySize, GSMEM);
        attr_set = true;
    }

    // 1. conversions
    convert_split3<<<NROWS, 256>>>(x, A2);
    transpose_split3<<<dim3(32, 32), 256>>>(Wq, Wtq);
    transpose_split3<<<dim3(32, 32), 256>>>(Wk, Wtk);
    transpose_split3<<<dim3(32, 32), 256>>>(Wv, Wtv);
    transpose_split3<<<dim3(32, 32), 256>>>(Wo, Wto);
    gates_prep32<<<32, 256>>>(Wa, Wb, Wab32);

    // 2. projections (tensor pipe via mma.sync)
    dim3 ggrid(1024 / 256, NROWS / 128);   // (4, 64)
    gemm_mma<<<ggrid, 256, GSMEM>>>(A2, Wtq, Qd);
    gemm_mma<<<ggrid, 256, GSMEM>>>(A2, Wtk, Kd);
    gemm_mma<<<ggrid, 256, GSMEM>>>(A2, Wtv, Vd);
    gates64<<<NROWS / 64, 256>>>(x, Wab32, ba, bb, al, be);

    // 3. normalize K, run the recurrence
    knorm_kernel<<<(NROWS * H_ * 32) / 256, 256>>>(Kd);
    scan_kernel<<<B_ * H_, 256>>>(Qd, Kd, Vd, al, be, S0, Yd, Sout);

    // 4. output projection
    convert_split3<<<NROWS, 256>>>(Yd, Y2);
    gemm_mma<<<ggrid, 256, GSMEM>>>(Y2, Wto, out);
}

// round 4
// speedup vs baseline: 2.0166x; 1.2732x over previous
#include <cuda_runtime.h>
#include <cuda_bf16.h>
#include <cstdint>
#include <math.h>

// Problem dims
constexpr int B_ = 4, T_ = 2048, DM_ = 1024, H_ = 16, D_ = 64;
constexpr int NROWS = B_ * T_;           // 8192
constexpr int KP = 3072;                 // 3-term split: [ah|al|ah] . [bh|bh|bl]
constexpr int STATE_ELEMS = B_ * H_ * D_ * D_;

// ---------------- scratch (device globals; allocation-free) ----------------
__device__ float g_QKV[(size_t)NROWS * 3072];   // fused Q|K|V fp32
__device__ float g_Y[(size_t)NROWS * DM_];
__device__ float g_alpha[NROWS * H_];
__device__ float g_beta[NROWS * H_];
__device__ float g_Sdump[STATE_ELEMS];
__device__ float g_Wab32[32 * DM_];
__device__ __nv_bfloat16 g_A2[(size_t)NROWS * KP];
__device__ __nv_bfloat16 g_Y2[(size_t)NROWS * KP];
__device__ __nv_bfloat16 g_Wqkv[(size_t)3072 * KP];   // rows: Wq|Wk|Wv cols
__device__ __nv_bfloat16 g_Wto[(size_t)DM_ * KP];

// ---------------------------------------------------------------------------
// bf16 mma.sync GEMM: C[8192, N] = A'[8192,3072] @ B'[N,3072]^T
// CTA 128x128, 8 warps (2M x 4N), warp tile 64x32, Kc=64, double-buffered
// cp.async, 2 CTAs/SM. smem rows padded to 72 halves (144B), conflict-free.
// ---------------------------------------------------------------------------
__global__ __launch_bounds__(256, 2) void gemm_mma(const __nv_bfloat16* __restrict__ A,
                                                   const __nv_bfloat16* __restrict__ Bw,
                                                   float* __restrict__ C, int ldc) {
    extern __shared__ char sm[];
    const int tid = threadIdx.x;
    const int lane = tid & 31, wid = tid >> 5;
    const int wm = wid & 1, wn = wid >> 1;       // 2 x 4 warp grid
    const int row0 = blockIdx.y * 128;
    const int col0 = blockIdx.x * 128;

    uint32_t sb;
    asm("{ .reg .u64 t; cvta.to.shared.u64 t, %1; cvt.u32.u64 %0, t; }" : "=r"(sb) : "l"(sm));

    // per-stage: A 128*72*2 = 18432 B, B same. stage = 36864; two stages.
    const uint32_t A_OFF[2] = {0u, 36864u};
    const uint32_t B_OFF[2] = {18432u, 36864u + 18432u};

    float acc[4][4][4];
#pragma unroll
    for (int i = 0; i < 4; ++i)
#pragma unroll
        for (int j = 0; j < 4; ++j)
#pragma unroll
            for (int q = 0; q < 4; ++q) acc[i][j][q] = 0.f;

    auto load_chunk = [&](int c, int buf) {
        const __nv_bfloat16* gA = A + (size_t)row0 * KP + c * 64;
        uint32_t ab = sb + A_OFF[buf];
#pragma unroll
        for (int l = 0; l < 4; ++l) {
            int idx = tid + (l << 8);
            int r = idx >> 3, s = idx & 7;
            uint32_t so = ab + (uint32_t)(r * 144 + s * 16);
            const void* gp = gA + (size_t)r * KP + s * 8;
            asm volatile("cp.async.cg.shared.global [%0], [%1], 16;" :: "r"(so), "l"(gp));
        }
        const __nv_bfloat16* gB = Bw + (size_t)col0 * KP + c * 64;
        uint32_t bbx = sb + B_OFF[buf];
#pragma unroll
        for (int l = 0; l < 4; ++l) {
            int idx = tid + (l << 8);
            int n = idx >> 3, s = idx & 7;
            uint32_t so = bbx + (uint32_t)(n * 144 + s * 16);
            const void* gp = gB + (size_t)n * KP + s * 8;
            asm volatile("cp.async.cg.shared.global [%0], [%1], 16;" :: "r"(so), "l"(gp));
        }
        asm volatile("cp.async.commit_group;" ::: "memory");
    };

    // per-lane ldmatrix base offsets (halves); layout verified in R3
    const uint32_t a_base = (uint32_t)((wm * 64 + (lane & 15)) * 72 + ((lane >> 4) << 3));
    const uint32_t b_base = (uint32_t)((wn * 32 + (((lane >> 4) & 1) << 3) + (lane & 7)) * 72 +
                                       (((lane >> 3) & 1) << 3));

    load_chunk(0, 0);

    constexpr int NCH = KP / 64;  // 48
    for (int c = 0; c < NCH; ++c) {
        const int buf = c & 1;
        if (c + 1 < NCH) {
            load_chunk(c + 1, buf ^ 1);
            asm volatile("cp.async.wait_group 1;" ::: "memory");
        } else {
            asm volatile("cp.async.wait_group 0;" ::: "memory");
        }
        __syncthreads();

        const uint32_t ab = sb + A_OFF[buf];
        const uint32_t bbs = sb + B_OFF[buf];
#pragma unroll
        for (int ks = 0; ks < 4; ++ks) {
            uint32_t af[4][4];
#pragma unroll
            for (int mi = 0; mi < 4; ++mi) {
                uint32_t addr = ab + (a_base + (uint32_t)(mi * 16 * 72 + ks * 16)) * 2;
                asm volatile("ldmatrix.sync.aligned.m8n8.x4.shared.b16 {%0,%1,%2,%3}, [%4];"
                             : "=r"(af[mi][0]), "=r"(af[mi][1]), "=r"(af[mi][2]), "=r"(af[mi][3])
                             : "r"(addr));
            }
            uint32_t bf[4][2];
#pragma unroll
            for (int nb = 0; nb < 2; ++nb) {
                uint32_t addr = bbs + (b_base + (uint32_t)(nb * 16 * 72 + ks * 16)) * 2;
                asm volatile("ldmatrix.sync.aligned.m8n8.x4.shared.b16 {%0,%1,%2,%3}, [%4];"
                             : "=r"(bf[2 * nb][0]), "=r"(bf[2 * nb][1]),
                               "=r"(bf[2 * nb + 1][0]), "=r"(bf[2 * nb + 1][1])
                             : "r"(addr));
            }
#pragma unroll
            for (int mi = 0; mi < 4; ++mi)
#pragma unroll
                for (int ni = 0; ni < 4; ++ni) {
                    asm volatile(
                        "mma.sync.aligned.m16n8k16.row.col.f32.bf16.bf16.f32 "
                        "{%0,%1,%2,%3}, {%4,%5,%6,%7}, {%8,%9}, {%0,%1,%2,%3};"
                        : "+f"(acc[mi][ni][0]), "+f"(acc[mi][ni][1]),
                          "+f"(acc[mi][ni][2]), "+f"(acc[mi][ni][3])
                        : "r"(af[mi][0]), "r"(af[mi][1]), "r"(af[mi][2]), "r"(af[mi][3]),
                          "r"(bf[ni][0]), "r"(bf[ni][1]));
                }
        }
        __syncthreads();
    }

    const int rb = row0 + wm * 64 + (lane >> 2);
    const int cb = col0 + wn * 32 + (lane & 3) * 2;
#pragma unroll
    for (int mi = 0; mi < 4; ++mi)
#pragma unroll
        for (int ni = 0; ni < 4; ++ni) {
            int r = rb + mi * 16, cc = cb + ni * 8;
            *(float2*)(C + (size_t)r * ldc + cc) = make_float2(acc[mi][ni][0], acc[mi][ni][1]);
            *(float2*)(C + (size_t)(r + 8) * ldc + cc) =
                make_float2(acc[mi][ni][2], acc[mi][ni][3]);
        }
}

// ---------------------------------------------------------------------------
// fp32 -> 3-term split bf16: out[m] = [hi(1024) | lo(1024) | hi(1024)]
// ---------------------------------------------------------------------------
__global__ __launch_bounds__(256) void convert_split3(const float* __restrict__ in,
                                                      __nv_bfloat16* __restrict__ out) {
    size_t i = (size_t)blockIdx.x * 256 + threadIdx.x;   // float4 group id
    float4 v = ((const float4*)in)[i];
    size_t m = i >> 8;
    int k4 = (int)(i & 255) << 2;
    __nv_bfloat16 h0 = __float2bfloat16(v.x), h1 = __float2bfloat16(v.y);
    __nv_bfloat16 h2 = __float2bfloat16(v.z), h3 = __float2bfloat16(v.w);
    __nv_bfloat16 l0 = __float2bfloat16(v.x - __bfloat162float(h0));
    __nv_bfloat16 l1 = __float2bfloat16(v.y - __bfloat162float(h1));
    __nv_bfloat16 l2 = __float2bfloat16(v.z - __bfloat162float(h2));
    __nv_bfloat16 l3 = __float2bfloat16(v.w - __bfloat162float(h3));
    __nv_bfloat162 hA = __halves2bfloat162(h0, h1), hB = __halves2bfloat162(h2, h3);
    __nv_bfloat162 lA = __halves2bfloat162(l0, l1), lB = __halves2bfloat162(l2, l3);
    __nv_bfloat162* o0 = (__nv_bfloat162*)(out + m * KP + k4);
    o0[0] = hA; o0[1] = hB;
    __nv_bfloat162* o1 = (__nv_bfloat162*)(out + m * KP + 1024 + k4);
    o1[0] = lA; o1[1] = lB;
    __nv_bfloat162* o2 = (__nv_bfloat162*)(out + m * KP + 2048 + k4);
    o2[0] = hA; o2[1] = hB;
}

// W[1024][1024] fp32 -> B'[n][3072] = [hi | hi | lo]  (transposed, K-major)
__global__ __launch_bounds__(256) void transpose_split3(const float* __restrict__ W,
                                                        __nv_bfloat16* __restrict__ out) {
    __shared__ float s[32][33];
    const int tx = threadIdx.x & 31, ty = threadIdx.x >> 5;
    const int k0 = blockIdx.y << 5, n0 = blockIdx.x << 5;
#pragma unroll
    for (int r = 0; r < 32; r += 8)
        s[ty + r][tx] = W[(size_t)(k0 + ty + r) * 1024 + n0 + tx];
    __syncthreads();
#pragma unroll
    for (int r = 0; r < 32; r += 8) {
        const int n = n0 + ty + r, k = k0 + tx;
        float v = s[tx][ty + r];
        __nv_bfloat16 h = __float2bfloat16(v);
        __nv_bfloat16 l = __float2bfloat16(v - __bfloat162float(h));
        out[(size_t)n * KP + k] = h;
        out[(size_t)n * KP + 1024 + k] = h;
        out[(size_t)n * KP + 2048 + k] = l;
    }
}

// Wa/Wb [1024][16] -> Wt32[32][1024] fp32
__global__ __launch_bounds__(256) void gates_prep32(const float* __restrict__ Wa,
                                                    const float* __restrict__ Wb,
                                                    float* __restrict__ out) {
    const int o = blockIdx.x;
    const float* W = (o < 16) ? Wa : Wb;
    const int h = o & 15;
    for (int k = threadIdx.x; k < 1024; k += 256)
        out[(size_t)o * 1024 + k] = W[k * 16 + h];
}

// ---------------------------------------------------------------------------
// Gates: logits = x @ Wt32^T, + bias, sigmoid. Block = 64 rows x 32 outputs.
// ---------------------------------------------------------------------------
__global__ __launch_bounds__(256) void gates64(const float* __restrict__ x,
                                               const float* __restrict__ Wt,
                                               const float* __restrict__ ba,
                                               const float* __restrict__ bb,
                                               float* __restrict__ alpha,
                                               float* __restrict__ beta) {
    __shared__ float xs[64][64];
    __shared__ float ws[32][65];
    const int tid = threadIdx.x;
    const int row0 = blockIdx.x * 64;
    const int rg = tid >> 5;
    const int o = tid & 31;

    float acc[8];
#pragma unroll
    for (int p = 0; p < 8; ++p) acc[p] = 0.f;

    for (int kc = 0; kc < 16; ++kc) {
        __syncthreads();
#pragma unroll
        for (int l = 0; l < 4; ++l) {
            int idx = tid + (l << 8);
            int r = idx >> 4, q = idx & 15;
            float4 v = *(const float4*)(x + (size_t)(row0 + r) * 1024 + kc * 64 + q * 4);
            *(float4*)(&xs[r][q * 4]) = v;
        }
#pragma unroll
        for (int l = 0; l < 2; ++l) {
            int idx = tid + (l << 8);
            int r = idx >> 4, q = idx & 15;
            float4 v = *(const float4*)(Wt + (size_t)r * 1024 + kc * 64 + q * 4);
            ws[r][q * 4 + 0] = v.x; ws[r][q * 4 + 1] = v.y;
            ws[r][q * 4 + 2] = v.z; ws[r][q * 4 + 3] = v.w;
        }
        __syncthreads();
#pragma unroll 8
        for (int k = 0; k < 64; ++k) {
            float wv = ws[o][k];
#pragma unroll
            for (int p = 0; p < 8; ++p)
                acc[p] = fmaf(xs[rg * 8 + p][k], wv, acc[p]);
        }
    }

    const float bias = (o < 16) ? ba[o] : bb[o - 16];
#pragma unroll
    for (int p = 0; p < 8; ++p) {
        float r = 1.f / (1.f + expf(-(acc[p] + bias)));
        int row = row0 + rg * 8 + p;
        if (o < 16) alpha[(size_t)row * 16 + o] = r;
        else        beta[(size_t)row * 16 + (o - 16)] = r;
    }
}

// ---------------------------------------------------------------------------
// K normalize over fused QKV buffer (K = cols [1024,2048))
// ---------------------------------------------------------------------------
__global__ __launch_bounds__(256) void knorm2(float* __restrict__ QKV) {
    const int w = (int)((blockIdx.x * blockDim.x + threadIdx.x) >> 5);
    const int lane = threadIdx.x & 31;
    if (w >= NROWS * H_) return;
    const int n = w >> 4, h = w & 15;
    float2* p = (float2*)(QKV + (size_t)n * 3072 + 1024 + h * 64);
    float2 v = p[lane];
    float ss = v.x * v.x + v.y * v.y;
#pragma unroll
    for (int m = 16; m; m >>= 1) ss += __shfl_xor_sync(~0u, ss, m);
    float inv = 1.f / fmaxf(sqrtf(ss), 1e-12f);
    v.x *= inv; v.y *= inv;
    p[lane] = v;
}

// ---------------------------------------------------------------------------
// Sequential scan: 128 blocks (one per (b,h,row-half)), 128 threads.
// Thread owns row i (of 32) and 16 cols. Reads fused QKV.
// ---------------------------------------------------------------------------
__global__ __launch_bounds__(128) void scan_kernel2(
    const float* __restrict__ QKV, const float* __restrict__ alpha,
    const float* __restrict__ beta, const float* __restrict__ S0,
    float* __restrict__ Y, float* __restrict__ Sout) {
    constexpr int CH = 16;
    __shared__ float cq[2][CH][64];
    __shared__ float ck[2][CH][64];
    __shared__ float cv[2][CH][32];
    __shared__ float ca[2][CH];
    __shared__ float cb[2][CH];

    const int tid = threadIdx.x;
    const int bh2 = blockIdx.x;          // 0..127
    const int bh = bh2 >> 1, half = bh2 & 1;
    const int b = bh >> 4, h = bh & 15;
    const int i = tid >> 2;              // row 0..31
    const int gi = half * 32 + i;        // row 0..63
    const int jg = tid & 3;
    const int j0 = jg << 4;

    float4 s4[4];
    {
        const float4* sp = (const float4*)(S0 + ((size_t)bh * 64 + gi) * 64 + j0);
        s4[0] = sp[0]; s4[1] = sp[1]; s4[2] = sp[2]; s4[3] = sp[3];
    }

    const float* rowQ = QKV + (size_t)b * T_ * 3072 + (size_t)h * 64;

    auto load_chunk = [&](int t0, int buf) {
#pragma unroll
        for (int l = 0; l < 2; ++l) {
            int idx = tid + (l << 7);
            int st = idx >> 4, f = (idx & 15) << 2;
            const float* base = rowQ + (size_t)(t0 + st) * 3072;
            *(float4*)(&cq[buf][st][f]) = *(const float4*)(base + f);
            *(float4*)(&ck[buf][st][f]) = *(const float4*)(base + 1024 + f);
        }
        {
            int st = tid >> 3, f = (tid & 7) << 2;
            const float* base = rowQ + (size_t)(t0 + st) * 3072 + 2048 + half * 32;
            *(float4*)(&cv[buf][st][f]) = *(const float4*)(base + f);
        }
        if (tid < CH)
            ca[buf][tid] = alpha[((size_t)b * T_ + t0 + tid) * H_ + h];
        else if (tid < 2 * CH)
            cb[buf][tid - CH] = beta[((size_t)b * T_ + t0 + tid - CH) * H_ + h];
    };

    const size_t ybase = (size_t)b * T_ * DM_ + (size_t)h * 64 + gi;
    const int nch = T_ / CH;
    load_chunk(0, 0);
    __syncthreads();

    for (int c = 0; c < nch; ++c) {
        const int buf = c & 1;
        if (c + 1 < nch) load_chunk((c + 1) * CH, buf ^ 1);

#pragma unroll 4
        for (int s = 0; s < CH; ++s) {
            const float a = ca[buf][s];
            const float bg = cb[buf][s];
            const float bv = bg * cv[buf][s][i];
            const float4* kp = (const float4*)(&ck[buf][s][j0]);
            const float4* qp = (const float4*)(&cq[buf][s][j0]);
            float partial = 0.f;
#pragma unroll
            for (int v = 0; v < 4; ++v) {
                float4 kk = kp[v];
                float4 qq = qp[v];
                s4[v].x = fmaf(a, s4[v].x, bv * kk.x); partial = fmaf(s4[v].x, qq.x, partial);
                s4[v].y = fmaf(a, s4[v].y, bv * kk.y); partial = fmaf(s4[v].y, qq.y, partial);
                s4[v].z = fmaf(a, s4[v].z, bv * kk.z); partial = fmaf(s4[v].z, qq.z, partial);
                s4[v].w = fmaf(a, s4[v].w, bv * kk.w); partial = fmaf(s4[v].w, qq.w, partial);
            }
            partial += __shfl_xor_sync(~0u, partial, 1);
            partial += __shfl_xor_sync(~0u, partial, 2);
            if (jg == 0)
                Y[ybase + (size_t)(c * CH + s) * DM_] = partial;
        }
        __syncthreads();
    }

    float4* so = (float4*)(Sout + ((size_t)bh * 64 + gi) * 64 + j0);
    so[0] = s4[0]; so[1] = s4[1]; so[2] = s4[2]; so[3] = s4[3];
}

// ---------------------------------------------------------------------------
extern "C" void kernel_launch(void* const* d_in, const int* in_sizes, int n_in,
                              void* d_out, int out_size) {
    (void)in_sizes; (void)n_in;
    const float* x  = (const float*)d_in[0];
    const float* S0 = (const float*)d_in[1];
    const float* Wq = (const float*)d_in[2];
    const float* Wk = (const float*)d_in[3];
    const float* Wv = (const float*)d_in[4];
    const float* Wa = (const float*)d_in[5];
    const float* ba = (const float*)d_in[6];
    const float* Wb = (const float*)d_in[7];
    const float* bb = (const float*)d_in[8];
    const float* Wo = (const float*)d_in[9];
    float* out = (float*)d_out;

    float *QKVd, *Yd, *al, *be, *Sdump, *Wab32;
    __nv_bfloat16 *A2, *Y2, *Wqkv, *Wto;
    cudaGetSymbolAddress((void**)&QKVd, g_QKV);
    cudaGetSymbolAddress((void**)&Yd, g_Y);
    cudaGetSymbolAddress((void**)&al, g_alpha);
    cudaGetSymbolAddress((void**)&be, g_beta);
    cudaGetSymbolAddress((void**)&Sdump, g_Sdump);
    cudaGetSymbolAddress((void**)&Wab32, g_Wab32);
    cudaGetSymbolAddress((void**)&A2, g_A2);
    cudaGetSymbolAddress((void**)&Y2, g_Y2);
    cudaGetSymbolAddress((void**)&Wqkv, g_Wqkv);
    cudaGetSymbolAddress((void**)&Wto, g_Wto);

    float* Sout = (out_size >= NROWS * DM_ + STATE_ELEMS) ? out + (size_t)NROWS * DM_ : Sdump;

    constexpr int GSMEM = 2 * 36864;   // 73728 per CTA
    cudaFuncSetAttribute(gemm_mma, cudaFuncAttributeMaxDynamicSharedMemorySize, GSMEM);

    // 1. conversions
    convert_split3<<<NROWS, 256>>>(x, A2);
    transpose_split3<<<dim3(32, 32), 256>>>(Wq, Wqkv);
    transpose_split3<<<dim3(32, 32), 256>>>(Wk, Wqkv + (size_t)1024 * KP);
    transpose_split3<<<dim3(32, 32), 256>>>(Wv, Wqkv + (size_t)2048 * KP);
    transpose_split3<<<dim3(32, 32), 256>>>(Wo, Wto);
    gates_prep32<<<32, 256>>>(Wa, Wb, Wab32);

    // 2. fused QKV projection (tensor pipe via mma.sync)
    gemm_mma<<<dim3(3072 / 128, NROWS / 128), 256, GSMEM>>>(A2, Wqkv, QKVd, 3072);
    gates64<<<NROWS / 64, 256>>>(x, Wab32, ba, bb, al, be);

    // 3. normalize K, run the recurrence (128-way parallel)
    knorm2<<<(NROWS * H_ * 32) / 256, 256>>>(QKVd);
    scan_kernel2<<<128, 128>>>(QKVd, al, be, S0, Yd, Sout);

    // 4. output projection
    convert_split3<<<NROWS, 256>>>(Yd, Y2);
    gemm_mma<<<dim3(1024 / 128, NROWS / 128), 256, GSMEM>>>(Y2, Wto, out, 1024);
}